// round 12
// baseline (speedup 1.0000x reference)
#include <cuda_runtime.h>

#define N_MODES   16
#define N_LAYERS  6
#define LIN_P     528           // 4*120 + 3*16
#define OUT_COLS  10
#define TPB       128
#define SPT       2             // samples per thread

typedef unsigned long long ull;

// ---------------------------------------------------------------------------
// Device-global scratch (allocation-free per harness rules)
// ---------------------------------------------------------------------------
__device__ float g_S[12][32][32];            // real symplectic mats
__device__ float g_W[N_LAYERS][32][32];      // composed weights, TRANSPOSED: [l][in][out]
__device__ float g_Wc[32][20];               // last layer compact: [in][x0..x9,p0..p9]
__device__ float g_d[N_LAYERS][32];          // displacements
__device__ float g_dc[20];                   // last-layer displacement, compact

// ---------------------------------------------------------------------------
// f32x2 packed-FMA helpers (Blackwell FFMA2)
// ---------------------------------------------------------------------------
__device__ __forceinline__ ull ffma2(ull a, ull b, ull c) {
    ull d;
    asm("fma.rn.f32x2 %0, %1, %2, %3;" : "=l"(d) : "l"(a), "l"(b), "l"(c));
    return d;
}
__device__ __forceinline__ ull dup_f32(float x) {
    ull d;
    unsigned int u = __float_as_uint(x);
    asm("mov.b64 %0, {%1, %1};" : "=l"(d) : "r"(u));
    return d;
}
__device__ __forceinline__ ull pack2(float x, float y) {
    ull d;
    asm("mov.b64 %0, {%1, %2};" : "=l"(d)
        : "r"(__float_as_uint(x)), "r"(__float_as_uint(y)));
    return d;
}
__device__ __forceinline__ void unpack2(ull a, float& x, float& y) {
    unsigned int lo, hi;
    asm("mov.b64 {%0, %1}, %2;" : "=r"(lo), "=r"(hi) : "l"(a));
    x = __uint_as_float(lo);
    y = __uint_as_float(hi);
}

// ---------------------------------------------------------------------------
// Setup kernel: build per-layer 32x32 affine maps from linear_params.
// One block, 1024 threads; compose phase staged via SMEM (~9us measured).
// ---------------------------------------------------------------------------
__global__ void setup_kernel(const float* __restrict__ lin) {
    int tid = threadIdx.x;
    __shared__ float s_scale[N_LAYERS][32];
    __shared__ float sS1[32][32];     // S1[k][i]   (broadcast reads)
    __shared__ float sS2[32][33];     // S2[o][k]   padded rows

    if (tid < 192) {
        // ---- interferometer scan: 12 groups x 16 threads, one column each ----
        int g   = tid >> 4;          // 0..11 = 2*layer + which
        int col = tid & 15;
        int l   = g >> 1;
        int w   = g & 1;
        const float* lp = lin + l * LIN_P;
        const float* th = lp + (w ? 256 : 0);
        const float* ph = lp + (w ? 376 : 120);

        float ur[16], ui[16];
        #pragma unroll
        for (int m = 0; m < 16; ++m) { ur[m] = (m == col) ? 1.f : 0.f; ui[m] = 0.f; }

        int k = 0;
        #pragma unroll
        for (int i = 0; i < 16; ++i) {
            #pragma unroll
            for (int j = i + 1; j < 16; ++j) {
                float t = th[k], p = ph[k];
                float s, c, sp, cp;
                __sincosf(t, &s, &c);
                __sincosf(p, &sp, &cp);
                float br = cp * s, bi = sp * s;      // e*s = (br, bi)
                float air = ur[i], aii = ui[i];
                float ajr = ur[j], aji = ui[j];
                ur[i] = c * air - (br * ajr + bi * aji);
                ui[i] = c * aii - (br * aji - bi * ajr);
                ur[j] = (br * air - bi * aii) + c * ajr;
                ui[j] = (br * aii + bi * air) + c * aji;
                ++k;
            }
        }
        #pragma unroll
        for (int m = 0; m < 16; ++m) {
            g_S[g][m][col]           =  ur[m];
            g_S[g][m][col + 16]      = -ui[m];
            g_S[g][m + 16][col]      =  ui[m];
            g_S[g][m + 16][col + 16] =  ur[m];
        }
    }

    if (tid < 192) {
        int l = tid >> 5, kk = tid & 31;
        const float* lp = lin + l * LIN_P;
        float r = lp[240 + (kk & 15)];
        s_scale[l][kk] = __expf(kk < 16 ? -r : r);
        g_d[l][kk] = lp[496 + kk];
    }
    __syncthreads();

    // ---- compose W[l][i][o] = sum_k S2[o][k]*scale[k]*S1[k][i] ----
    {
        int r = tid >> 5, c = tid & 31;
        #pragma unroll 1
        for (int l = 0; l < N_LAYERS; ++l) {
            sS1[r][c] = g_S[2 * l][r][c];          // coalesced 128B rows
            sS2[r][c] = g_S[2 * l + 1][r][c];
            __syncthreads();
            int i = r, o = c;
            float acc = 0.f;
            #pragma unroll
            for (int k = 0; k < 32; ++k)
                acc += sS2[o][k] * (s_scale[l][k] * sS1[k][i]);
            g_W[l][i][o] = acc;
            __syncthreads();
        }
    }

    // ---- compact last layer: keep only outputs {0..9, 16..25} ----
    if (tid < 640) {
        int i = tid / 20, j = tid % 20;
        g_Wc[i][j] = g_W[N_LAYERS - 1][i][j < 10 ? j : j + 6];
    }
    if (tid < 20) g_dc[tid] = g_d[N_LAYERS - 1][tid < 10 ? tid : tid + 6];
}

// ---------------------------------------------------------------------------
// Affine layer on NS samples: one LDS.128 of weights feeds 2*NS FFMA2s.
// W laid out [in][out], STRIDE floats per row; NP output f32x2 pairs.
// ---------------------------------------------------------------------------
template<int NS, int NIN, int NP, int STRIDE>
__device__ __forceinline__ void linearN(float (&v)[NS][32],
                                        const float* __restrict__ W,
                                        const float* __restrict__ dv) {
    ull acc[NS][NP];
    #pragma unroll
    for (int k = 0; k < NP; ++k) {
        ull t = pack2(dv[2 * k], dv[2 * k + 1]);
        #pragma unroll
        for (int s = 0; s < NS; ++s) acc[s][k] = t;
    }
    #pragma unroll
    for (int i = 0; i < NIN; ++i) {
        ull dm[NS];
        #pragma unroll
        for (int s = 0; s < NS; ++s) dm[s] = dup_f32(v[s][i]);
        const ulonglong2* wr = reinterpret_cast<const ulonglong2*>(W + i * STRIDE);
        #pragma unroll
        for (int q = 0; q < NP / 2; ++q) {
            ulonglong2 w2 = wr[q];                 // 4 weights = 2 output pairs
            #pragma unroll
            for (int s = 0; s < NS; ++s) {
                acc[s][2 * q]     = ffma2(dm[s], w2.x, acc[s][2 * q]);
                acc[s][2 * q + 1] = ffma2(dm[s], w2.y, acc[s][2 * q + 1]);
            }
        }
    }
    #pragma unroll
    for (int k = 0; k < NP; ++k)
        #pragma unroll
        for (int s = 0; s < NS; ++s)
            unpack2(acc[s][k], v[s][2 * k], v[s][2 * k + 1]);
}

// MUFU-based kerr: sincos runs on the MUFU pipe, overlapping the contended
// fma pipe (R11 showed the polynomial version moves this work ONTO fma: no win).
__device__ __forceinline__ void kerr16(float* v, const float* __restrict__ kp) {
    #pragma unroll
    for (int m = 0; m < 16; ++m) {
        float x = v[m], p = v[m + 16];
        float ang = kp[m] * (x * x + p * p);
        float s, c;
        __sincosf(ang, &s, &c);
        v[m]      = fmaf(c, x,  s * p);
        v[m + 16] = fmaf(c, p, -s * x);
    }
}

// ---------------------------------------------------------------------------
// Main kernel: SPT samples per thread; state in registers; weights in SMEM.
// __launch_bounds__(TPB, 4): cap regs at 128 -> 4 CTAs = 16 warps/SM
// (4/SMSP). R6-R11 all ran 12 warps at ~50% issue, latency-bound; intrinsic
// working set is ~96 regs (64 state + 32 acc), the 168 was allocator slack.
// ---------------------------------------------------------------------------
__global__ void __launch_bounds__(TPB, 4) qnet_main(
    const float* __restrict__ batch,
    const float* __restrict__ act_p,      // (5, 16)
    const float* __restrict__ last_act,   // (16,)
    float* __restrict__ out,
    int n_samples)
{
    __shared__ __align__(16) float sW[N_LAYERS - 1][32][32];  // layers 0..4: 20 KB
    __shared__ __align__(16) float sWc[32][20];               // layer 5 compact
    __shared__ float sd[N_LAYERS - 1][32];
    __shared__ float sdc[20];
    __shared__ float sk[N_LAYERS][16];

    int tid = threadIdx.x;
    {
        const float4* src = reinterpret_cast<const float4*>(g_W);
        float4* dst = reinterpret_cast<float4*>(&sW[0][0][0]);
        for (int idx = tid; idx < (N_LAYERS - 1) * 32 * 32 / 4; idx += TPB) dst[idx] = src[idx];
        const float4* srcc = reinterpret_cast<const float4*>(&g_Wc[0][0]);
        float4* dstc = reinterpret_cast<float4*>(&sWc[0][0]);
        for (int idx = tid; idx < 32 * 20 / 4; idx += TPB) dstc[idx] = srcc[idx];
        for (int idx = tid; idx < (N_LAYERS - 1) * 32; idx += TPB)
            (&sd[0][0])[idx] = (&g_d[0][0])[idx];
        if (tid < 20) sdc[tid] = g_dc[tid];
        if (tid < 80)       (&sk[0][0])[tid] = act_p[tid];
        else if (tid < 96)  (&sk[0][0])[tid] = last_act[tid - 80];
    }
    __syncthreads();

    int s0 = blockIdx.x * (TPB * SPT) + tid;          // sample of slot 0

    float v[SPT][32];
    #pragma unroll
    for (int s = 0; s < SPT; ++s) {
        int sid = s0 + s * TPB;                       // coalesced within warp
        const float4* br = reinterpret_cast<const float4*>(batch + (size_t)sid * 16);
        #pragma unroll
        for (int q = 0; q < 4; ++q) {
            float4 t = (sid < n_samples) ? br[q] : make_float4(0.f, 0.f, 0.f, 0.f);
            v[s][4 * q] = t.x; v[s][4 * q + 1] = t.y;
            v[s][4 * q + 2] = t.z; v[s][4 * q + 3] = t.w;
        }
        #pragma unroll
        for (int m = 16; m < 32; ++m) v[s][m] = 0.f;
    }

    // layer 0: inputs 16..31 are zero -> only 16 i-steps
    linearN<SPT, 16, 16, 32>(v, &sW[0][0][0], &sd[0][0]);
    #pragma unroll
    for (int s = 0; s < SPT; ++s) kerr16(v[s], &sk[0][0]);

    #pragma unroll 1
    for (int l = 1; l < N_LAYERS - 1; ++l) {
        linearN<SPT, 32, 16, 32>(v, &sW[l][0][0], &sd[l][0]);
        #pragma unroll
        for (int s = 0; s < SPT; ++s) kerr16(v[s], &sk[l][0]);
    }

    // last layer: only outputs x0..x9 (cols 0..9) and p0..p9 (cols 10..19)
    linearN<SPT, 32, 10, 20>(v, &sWc[0][0], sdc);

    #pragma unroll
    for (int s = 0; s < SPT; ++s) {
        int sid = s0 + s * TPB;
        float o10[OUT_COLS];
        #pragma unroll
        for (int m = 0; m < OUT_COLS; ++m) {
            float ka = sk[N_LAYERS - 1][m];
            float x = v[s][m], p = v[s][10 + m];
            float ang = ka * (x * x + p * p);
            float sn, cs;
            __sincosf(ang, &sn, &cs);
            o10[m] = fmaf(cs, x, sn * p);
        }
        if (sid < n_samples) {
            float2* orow = reinterpret_cast<float2*>(out + (size_t)sid * OUT_COLS);
            #pragma unroll
            for (int m = 0; m < 5; ++m) orow[m] = make_float2(o10[2 * m], o10[2 * m + 1]);
        }
    }
}

// ---------------------------------------------------------------------------
extern "C" void kernel_launch(void* const* d_in, const int* in_sizes, int n_in,
                              void* d_out, int out_size) {
    const float* batch    = (const float*)d_in[0];   // (B, 16)
    const float* lin      = (const float*)d_in[1];   // (6, 528)
    const float* act_p    = (const float*)d_in[2];   // (5, 16)
    const float* last_act = (const float*)d_in[3];   // (16,)
    float* out = (float*)d_out;

    int n_samples = in_sizes[0] / N_MODES;
    int blocks = (n_samples + TPB * SPT - 1) / (TPB * SPT);

    setup_kernel<<<1, 1024>>>(lin);
    qnet_main<<<blocks, TPB>>>(batch, act_p, last_act, out, n_samples);
}

// round 14
// speedup vs baseline: 2.4919x; 2.4919x over previous
#include <cuda_runtime.h>
#include <cuda_bf16.h>

#define N_MODES   16
#define N_LAYERS  6
#define LIN_P     528
#define OUT_COLS  10
#define TPB       128            // 4 warps, 16 samples/warp -> 64 samples/CTA

// ---------------------------------------------------------------------------
// Device-global scratch (allocation-free per harness rules)
// ---------------------------------------------------------------------------
__device__ float g_S[12][32][32];          // real symplectic mats
__device__ float g_d[N_LAYERS][32];        // displacements
// Per-lane B fragments for mma.m16n8k16 (B[k][n] = E[n][k], bf16x2-packed):
// [layer][ktile][ntile][lane] = {b0, b1}
__device__ uint2 g_Bf[N_LAYERS][2][4][32];

// ---------------------------------------------------------------------------
// helpers
// ---------------------------------------------------------------------------
__device__ __forceinline__ unsigned pack_bf16x2(float lo, float hi) {
    unsigned r;
    asm("cvt.rn.bf16x2.f32 %0, %1, %2;" : "=r"(r) : "f"(hi), "f"(lo));
    return r;
}
// D = A@B + C, bf16 inputs, f32 accum. A row-major, B col-major.
__device__ __forceinline__ void mma16816(float& c0, float& c1, float& c2, float& c3,
                                         unsigned a0, unsigned a1, unsigned a2, unsigned a3,
                                         unsigned b0, unsigned b1) {
    asm("mma.sync.aligned.m16n8k16.row.col.f32.bf16.bf16.f32 "
        "{%0,%1,%2,%3}, {%4,%5,%6,%7}, {%8,%9}, {%0,%1,%2,%3};"
        : "+f"(c0), "+f"(c1), "+f"(c2), "+f"(c3)
        : "r"(a0), "r"(a1), "r"(a2), "r"(a3), "r"(b0), "r"(b1));
}

// ---------------------------------------------------------------------------
// Setup kernel: build E = W - I per layer, emit bf16 B-fragments + d.
// One block, 1024 threads.
// ---------------------------------------------------------------------------
__global__ void setup_kernel(const float* __restrict__ lin) {
    int tid = threadIdx.x;
    __shared__ float s_scale[N_LAYERS][32];
    __shared__ float sS1[32][32];     // S1[k][i]
    __shared__ float sS2[32][33];     // S2[o][k] padded
    __shared__ float sE[32][33];      // E[o][i]  padded

    if (tid < 192) {
        // ---- interferometer scan: 12 groups x 16 threads, one column each ----
        int g = tid >> 4, col = tid & 15;
        int l = g >> 1, w = g & 1;
        const float* lp = lin + l * LIN_P;
        const float* th = lp + (w ? 256 : 0);
        const float* ph = lp + (w ? 376 : 120);

        float ur[16], ui[16];
        #pragma unroll
        for (int m = 0; m < 16; ++m) { ur[m] = (m == col) ? 1.f : 0.f; ui[m] = 0.f; }
        int k = 0;
        #pragma unroll
        for (int i = 0; i < 16; ++i) {
            #pragma unroll
            for (int j = i + 1; j < 16; ++j) {
                float t = th[k], p = ph[k];
                float s, c, sp, cp;
                __sincosf(t, &s, &c);
                __sincosf(p, &sp, &cp);
                float br = cp * s, bi = sp * s;
                float air = ur[i], aii = ui[i];
                float ajr = ur[j], aji = ui[j];
                ur[i] = c * air - (br * ajr + bi * aji);
                ui[i] = c * aii - (br * aji - bi * ajr);
                ur[j] = (br * air - bi * aii) + c * ajr;
                ui[j] = (br * aii + bi * air) + c * aji;
                ++k;
            }
        }
        #pragma unroll
        for (int m = 0; m < 16; ++m) {
            g_S[g][m][col]           =  ur[m];
            g_S[g][m][col + 16]      = -ui[m];
            g_S[g][m + 16][col]      =  ui[m];
            g_S[g][m + 16][col + 16] =  ur[m];
        }
    }
    if (tid < 192) {
        int l = tid >> 5, kk = tid & 31;
        const float* lp = lin + l * LIN_P;
        float r = lp[240 + (kk & 15)];
        s_scale[l][kk] = __expf(kk < 16 ? -r : r);
        g_d[l][kk] = lp[496 + kk];
    }
    __syncthreads();

    // compose E = S2*diag(scale)*S1 - I, then pack B fragments per layer
    int o = tid >> 5, i = tid & 31;
    #pragma unroll 1
    for (int l = 0; l < N_LAYERS; ++l) {
        sS1[o][i] = g_S[2 * l][o][i];
        sS2[o][i] = g_S[2 * l + 1][o][i];
        __syncthreads();
        float acc = 0.f;
        #pragma unroll
        for (int k = 0; k < 32; ++k)
            acc += sS2[o][k] * (s_scale[l][k] * sS1[k][i]);
        sE[o][i] = acc - ((i == o) ? 1.f : 0.f);
        __syncthreads();

        // B fragments: 2 ktiles x 4 ntiles x 32 lanes = 256 threads
        if (tid < 256) {
            int lane = tid & 31;
            int nt   = (tid >> 5) & 3;
            int kt   = tid >> 7;
            int n    = nt * 8 + (lane >> 2);
            int k0   = kt * 16 + 2 * (lane & 3);
            uint2 b;
            b.x = pack_bf16x2(sE[n][k0],     sE[n][k0 + 1]);
            b.y = pack_bf16x2(sE[n][k0 + 8], sE[n][k0 + 9]);
            g_Bf[l][kt][nt][lane] = b;
        }
        __syncthreads();
    }
}

// ---------------------------------------------------------------------------
// Main kernel: warp = 16 samples. State vC[4][4] in C-fragment layout
// (ntile x {c0..c3}); C->A fragment identity chains layers with zero
// shuffles/smem. v_new = v + E@v + d via one f32-accum MMA pass + Kerr.
// ---------------------------------------------------------------------------
__global__ void __launch_bounds__(TPB) qnet_main(
    const float* __restrict__ batch,
    const float* __restrict__ act_p,      // (5,16)
    const float* __restrict__ last_act,   // (16,)
    float* __restrict__ out,
    int n_samples)
{
    int tid  = threadIdx.x;
    int warp = tid >> 5;
    int lane = tid & 31;
    int qr   = lane >> 2;                 // row-in-tile 0..7
    int c0   = 2 * (lane & 3);            // col base within n-tile

    int r0 = blockIdx.x * 64 + warp * 16 + qr;
    int r1 = r0 + 8;
    bool v0 = r0 < n_samples, v1 = r1 < n_samples;

    // ---- load input into C-fragment layout ----
    float vC[4][4];
    #pragma unroll
    for (int nt = 0; nt < 2; ++nt) {
        float2 t0 = v0 ? *reinterpret_cast<const float2*>(batch + (size_t)r0 * 16 + nt * 8 + c0)
                       : make_float2(0.f, 0.f);
        float2 t1 = v1 ? *reinterpret_cast<const float2*>(batch + (size_t)r1 * 16 + nt * 8 + c0)
                       : make_float2(0.f, 0.f);
        vC[nt][0] = t0.x; vC[nt][1] = t0.y;
        vC[nt][2] = t1.x; vC[nt][3] = t1.y;
    }
    #pragma unroll
    for (int nt = 2; nt < 4; ++nt)
        #pragma unroll
        for (int j = 0; j < 4; ++j) vC[nt][j] = 0.f;

    #pragma unroll
    for (int l = 0; l < N_LAYERS; ++l) {
        // acc = v + d
        float acc[4][4];
        #pragma unroll
        for (int nt = 0; nt < 4; ++nt) {
            int col = nt * 8 + c0;
            float d0 = __ldg(&g_d[l][col]);
            float d1 = __ldg(&g_d[l][col + 1]);
            acc[nt][0] = vC[nt][0] + d0;
            acc[nt][1] = vC[nt][1] + d1;
            acc[nt][2] = vC[nt][2] + d0;
            acc[nt][3] = vC[nt][3] + d1;
        }
        // acc += E @ v   (layer 0: k-cols 16..31 of v are zero -> 1 k-tile)
        int klim = (l == 0) ? 1 : 2;
        #pragma unroll
        for (int kt = 0; kt < 2; ++kt) {
            if (kt >= klim) break;
            unsigned a0 = pack_bf16x2(vC[2 * kt][0],     vC[2 * kt][1]);
            unsigned a1 = pack_bf16x2(vC[2 * kt][2],     vC[2 * kt][3]);
            unsigned a2 = pack_bf16x2(vC[2 * kt + 1][0], vC[2 * kt + 1][1]);
            unsigned a3 = pack_bf16x2(vC[2 * kt + 1][2], vC[2 * kt + 1][3]);
            #pragma unroll
            for (int nt = 0; nt < 4; ++nt) {
                uint2 b = __ldg(&g_Bf[l][kt][nt][lane]);
                mma16816(acc[nt][0], acc[nt][1], acc[nt][2], acc[nt][3],
                         a0, a1, a2, a3, b.x, b.y);
            }
        }
        #pragma unroll
        for (int nt = 0; nt < 4; ++nt)
            #pragma unroll
            for (int j = 0; j < 4; ++j) vC[nt][j] = acc[nt][j];

        // Kerr (layers 0..4): x in ntiles 0,1; p in ntiles 2,3 (same reg idx)
        if (l < N_LAYERS - 1) {
            float k0 = __ldg(act_p + l * 16 + c0);
            float k1 = __ldg(act_p + l * 16 + c0 + 1);
            float k2 = __ldg(act_p + l * 16 + c0 + 8);
            float k3 = __ldg(act_p + l * 16 + c0 + 9);
            #pragma unroll
            for (int nt = 0; nt < 2; ++nt) {
                #pragma unroll
                for (int j = 0; j < 4; ++j) {
                    float kp = nt ? ((j & 1) ? k3 : k2) : ((j & 1) ? k1 : k0);
                    float x = vC[nt][j], p = vC[nt + 2][j];
                    float ang = kp * (x * x + p * p);
                    float s, c;
                    __sincosf(ang, &s, &c);
                    vC[nt][j]     = fmaf(c, x,  s * p);
                    vC[nt + 2][j] = fmaf(c, p, -s * x);
                }
            }
        }
    }

    // ---- last activation (modes < 10 stored; extra lanes computed, unstored)
    float o0[4], o1[4];
    {
        float k0 = __ldg(last_act + c0);
        float k1 = __ldg(last_act + c0 + 1);
        float k2 = __ldg(last_act + c0 + 8);
        float k3 = __ldg(last_act + c0 + 9);
        #pragma unroll
        for (int j = 0; j < 4; ++j) {
            float kp = (j & 1) ? k1 : k0;
            float x = vC[0][j], p = vC[2][j];
            float ang = kp * (x * x + p * p);
            float s, c;
            __sincosf(ang, &s, &c);
            o0[j] = fmaf(c, x, s * p);
            kp = (j & 1) ? k3 : k2;
            x = vC[1][j]; p = vC[3][j];
            ang = kp * (x * x + p * p);
            __sincosf(ang, &s, &c);
            o1[j] = fmaf(c, x, s * p);
        }
    }

    // ---- store: cols c0,c0+1 (always) and cols 8,9 (lanes with c0==0) ----
    if (v0) {
        *reinterpret_cast<float2*>(out + (size_t)r0 * OUT_COLS + c0) = make_float2(o0[0], o0[1]);
        if (c0 == 0)
            *reinterpret_cast<float2*>(out + (size_t)r0 * OUT_COLS + 8) = make_float2(o1[0], o1[1]);
    }
    if (v1) {
        *reinterpret_cast<float2*>(out + (size_t)r1 * OUT_COLS + c0) = make_float2(o0[2], o0[3]);
        if (c0 == 0)
            *reinterpret_cast<float2*>(out + (size_t)r1 * OUT_COLS + 8) = make_float2(o1[2], o1[3]);
    }
}

// ---------------------------------------------------------------------------
extern "C" void kernel_launch(void* const* d_in, const int* in_sizes, int n_in,
                              void* d_out, int out_size) {
    const float* batch    = (const float*)d_in[0];   // (B,16)
    const float* lin      = (const float*)d_in[1];   // (6,528)
    const float* act_p    = (const float*)d_in[2];   // (5,16)
    const float* last_act = (const float*)d_in[3];   // (16,)
    float* out = (float*)d_out;

    int n_samples = in_sizes[0] / N_MODES;
    int blocks = (n_samples + 63) / 64;

    setup_kernel<<<1, 1024>>>(lin);
    qnet_main<<<blocks, TPB>>>(batch, act_p, last_act, out, n_samples);
}

// round 15
// speedup vs baseline: 2.5463x; 1.0218x over previous
#include <cuda_runtime.h>
#include <cuda_bf16.h>

#define N_MODES   16
#define N_LAYERS  6
#define LIN_P     528
#define OUT_COLS  10
#define TPB       128            // 4 warps x 32 samples -> 128 samples/CTA

// ---------------------------------------------------------------------------
// Device-global scratch (allocation-free per harness rules)
// ---------------------------------------------------------------------------
__device__ float g_S[12][32][32];          // real symplectic mats
__device__ float g_d[N_LAYERS][32];        // displacements (raw)
// Per-lane B fragments for mma.m16n8k16 (B[k][n] = E[n][k], bf16x2-packed):
__device__ uint2  g_Bf[N_LAYERS][2][4][32];   // [layer][ktile][ntile][lane]
// Fragment-packed params: one vector load replaces 4-8 scalar LDGs
__device__ float4 g_df[N_LAYERS][2][32];      // [layer][half][lane]:
                                              //   half0={d[c0],d[c0+1],d[8+c0],d[8+c0+1]}
                                              //   half1= same +16
__device__ float4 g_kf[N_LAYERS][32];         // kerr {k[c0],k[c0+1],k[c0+8],k[c0+9]}

// ---------------------------------------------------------------------------
// helpers
// ---------------------------------------------------------------------------
__device__ __forceinline__ unsigned pack_bf16x2(float lo, float hi) {
    unsigned r;
    asm("cvt.rn.bf16x2.f32 %0, %1, %2;" : "=r"(r) : "f"(hi), "f"(lo));
    return r;
}
__device__ __forceinline__ void mma16816(float& c0, float& c1, float& c2, float& c3,
                                         unsigned a0, unsigned a1, unsigned a2, unsigned a3,
                                         unsigned b0, unsigned b1) {
    asm("mma.sync.aligned.m16n8k16.row.col.f32.bf16.bf16.f32 "
        "{%0,%1,%2,%3}, {%4,%5,%6,%7}, {%8,%9}, {%0,%1,%2,%3};"
        : "+f"(c0), "+f"(c1), "+f"(c2), "+f"(c3)
        : "r"(a0), "r"(a1), "r"(a2), "r"(a3), "r"(b0), "r"(b1));
}

// ---------------------------------------------------------------------------
// Setup kernel: E = W - I per layer -> bf16 B-fragments; pack d/kerr frags.
// One block, 1024 threads.
// ---------------------------------------------------------------------------
__global__ void setup_kernel(const float* __restrict__ lin,
                             const float* __restrict__ act_p,
                             const float* __restrict__ last_act) {
    int tid = threadIdx.x;
    __shared__ float s_scale[N_LAYERS][32];
    __shared__ float sS1[32][32];     // S1[k][i]
    __shared__ float sS2[32][33];     // S2[o][k] padded
    __shared__ float sE[32][33];      // E[o][i]  padded

    if (tid < 192) {
        // ---- interferometer scan: 12 groups x 16 threads, one column each ----
        int g = tid >> 4, col = tid & 15;
        int l = g >> 1, w = g & 1;
        const float* lp = lin + l * LIN_P;
        const float* th = lp + (w ? 256 : 0);
        const float* ph = lp + (w ? 376 : 120);

        float ur[16], ui[16];
        #pragma unroll
        for (int m = 0; m < 16; ++m) { ur[m] = (m == col) ? 1.f : 0.f; ui[m] = 0.f; }
        int k = 0;
        #pragma unroll
        for (int i = 0; i < 16; ++i) {
            #pragma unroll
            for (int j = i + 1; j < 16; ++j) {
                float t = th[k], p = ph[k];
                float s, c, sp, cp;
                __sincosf(t, &s, &c);
                __sincosf(p, &sp, &cp);
                float br = cp * s, bi = sp * s;
                float air = ur[i], aii = ui[i];
                float ajr = ur[j], aji = ui[j];
                ur[i] = c * air - (br * ajr + bi * aji);
                ui[i] = c * aii - (br * aji - bi * ajr);
                ur[j] = (br * air - bi * aii) + c * ajr;
                ui[j] = (br * aii + bi * air) + c * aji;
                ++k;
            }
        }
        #pragma unroll
        for (int m = 0; m < 16; ++m) {
            g_S[g][m][col]           =  ur[m];
            g_S[g][m][col + 16]      = -ui[m];
            g_S[g][m + 16][col]      =  ui[m];
            g_S[g][m + 16][col + 16] =  ur[m];
        }
    }
    if (tid < 192) {
        int l = tid >> 5, kk = tid & 31;
        const float* lp = lin + l * LIN_P;
        float r = lp[240 + (kk & 15)];
        s_scale[l][kk] = __expf(kk < 16 ? -r : r);
        g_d[l][kk] = lp[496 + kk];
    }
    __syncthreads();

    // compose E = S2*diag(scale)*S1 - I, pack B fragments per layer
    int o = tid >> 5, i = tid & 31;
    #pragma unroll 1
    for (int l = 0; l < N_LAYERS; ++l) {
        sS1[o][i] = g_S[2 * l][o][i];
        sS2[o][i] = g_S[2 * l + 1][o][i];
        __syncthreads();
        float acc = 0.f;
        #pragma unroll
        for (int k = 0; k < 32; ++k)
            acc += sS2[o][k] * (s_scale[l][k] * sS1[k][i]);
        sE[o][i] = acc - ((i == o) ? 1.f : 0.f);
        __syncthreads();

        if (tid < 256) {
            int lane = tid & 31;
            int nt   = (tid >> 5) & 3;
            int kt   = tid >> 7;
            int n    = nt * 8 + (lane >> 2);
            int k0   = kt * 16 + 2 * (lane & 3);
            uint2 b;
            b.x = pack_bf16x2(sE[n][k0],     sE[n][k0 + 1]);
            b.y = pack_bf16x2(sE[n][k0 + 8], sE[n][k0 + 9]);
            g_Bf[l][kt][nt][lane] = b;
        }
        __syncthreads();
    }

    // pack d fragments: [l][half][lane]
    if (tid < N_LAYERS * 2 * 32) {
        int lane = tid & 31, half = (tid >> 5) & 1, l = tid >> 6;
        int c0 = 2 * (lane & 3) + half * 16;
        g_df[l][half][tid & 31] = make_float4(g_d[l][c0], g_d[l][c0 + 1],
                                              g_d[l][c0 + 8], g_d[l][c0 + 9]);
    }
    // pack kerr fragments: [l][lane] (l=5 from last_act)
    if (tid < N_LAYERS * 32) {
        int lane = tid & 31, l = tid >> 5;
        const float* kp = (l < N_LAYERS - 1) ? (act_p + l * 16) : last_act;
        int c0 = 2 * (lane & 3);
        g_kf[l][lane] = make_float4(kp[c0], kp[c0 + 1], kp[c0 + 8], kp[c0 + 9]);
    }
}

// ---------------------------------------------------------------------------
// Main kernel: warp = 32 samples (2 row-blocks of 16); B/d/kerr loads shared
// across both row-blocks -> per-sample L1 traffic halved vs R14.
// ---------------------------------------------------------------------------
__global__ void __launch_bounds__(TPB) qnet_main(
    const float* __restrict__ batch,
    float* __restrict__ out,
    int n_samples)
{
    int tid  = threadIdx.x;
    int warp = tid >> 5;
    int lane = tid & 31;
    int qr   = lane >> 2;                 // row-in-tile 0..7
    int c0   = 2 * (lane & 3);            // col base within n-tile

    int base = blockIdx.x * 128 + warp * 32;
    int r[2][2];
    r[0][0] = base + qr;       r[0][1] = base + qr + 8;
    r[1][0] = base + 16 + qr;  r[1][1] = base + 16 + qr + 8;

    // ---- load input into C-fragment layout: vC[rb][nt][j] ----
    float vC[2][4][4];
    #pragma unroll
    for (int rb = 0; rb < 2; ++rb) {
        #pragma unroll
        for (int nt = 0; nt < 2; ++nt) {
            float2 t0 = (r[rb][0] < n_samples)
                ? *reinterpret_cast<const float2*>(batch + (size_t)r[rb][0] * 16 + nt * 8 + c0)
                : make_float2(0.f, 0.f);
            float2 t1 = (r[rb][1] < n_samples)
                ? *reinterpret_cast<const float2*>(batch + (size_t)r[rb][1] * 16 + nt * 8 + c0)
                : make_float2(0.f, 0.f);
            vC[rb][nt][0] = t0.x; vC[rb][nt][1] = t0.y;
            vC[rb][nt][2] = t1.x; vC[rb][nt][3] = t1.y;
        }
        #pragma unroll
        for (int nt = 2; nt < 4; ++nt)
            #pragma unroll
            for (int j = 0; j < 4; ++j) vC[rb][nt][j] = 0.f;
    }

    #pragma unroll
    for (int l = 0; l < N_LAYERS; ++l) {
        float4 d0 = __ldg(&g_df[l][0][lane]);   // cols {c0,c0+1,8+c0,8+c0+1}
        float4 d1 = __ldg(&g_df[l][1][lane]);   // +16

        float acc[2][4][4];
        #pragma unroll
        for (int rb = 0; rb < 2; ++rb) {
            acc[rb][0][0] = vC[rb][0][0] + d0.x; acc[rb][0][1] = vC[rb][0][1] + d0.y;
            acc[rb][0][2] = vC[rb][0][2] + d0.x; acc[rb][0][3] = vC[rb][0][3] + d0.y;
            acc[rb][1][0] = vC[rb][1][0] + d0.z; acc[rb][1][1] = vC[rb][1][1] + d0.w;
            acc[rb][1][2] = vC[rb][1][2] + d0.z; acc[rb][1][3] = vC[rb][1][3] + d0.w;
            acc[rb][2][0] = vC[rb][2][0] + d1.x; acc[rb][2][1] = vC[rb][2][1] + d1.y;
            acc[rb][2][2] = vC[rb][2][2] + d1.x; acc[rb][2][3] = vC[rb][2][3] + d1.y;
            acc[rb][3][0] = vC[rb][3][0] + d1.z; acc[rb][3][1] = vC[rb][3][1] + d1.w;
            acc[rb][3][2] = vC[rb][3][2] + d1.z; acc[rb][3][3] = vC[rb][3][3] + d1.w;
        }

        // acc += E @ v  (layer 0: k-cols 16..31 of v are zero -> 1 k-tile)
        const int klim = (l == 0) ? 1 : 2;
        #pragma unroll
        for (int kt = 0; kt < 2; ++kt) {
            if (kt >= klim) break;
            unsigned a[2][4];
            #pragma unroll
            for (int rb = 0; rb < 2; ++rb) {
                a[rb][0] = pack_bf16x2(vC[rb][2 * kt][0],     vC[rb][2 * kt][1]);
                a[rb][1] = pack_bf16x2(vC[rb][2 * kt][2],     vC[rb][2 * kt][3]);
                a[rb][2] = pack_bf16x2(vC[rb][2 * kt + 1][0], vC[rb][2 * kt + 1][1]);
                a[rb][3] = pack_bf16x2(vC[rb][2 * kt + 1][2], vC[rb][2 * kt + 1][3]);
            }
            #pragma unroll
            for (int nt = 0; nt < 4; ++nt) {
                uint2 b = __ldg(&g_Bf[l][kt][nt][lane]);
                #pragma unroll
                for (int rb = 0; rb < 2; ++rb)
                    mma16816(acc[rb][nt][0], acc[rb][nt][1], acc[rb][nt][2], acc[rb][nt][3],
                             a[rb][0], a[rb][1], a[rb][2], a[rb][3], b.x, b.y);
            }
        }
        #pragma unroll
        for (int rb = 0; rb < 2; ++rb)
            #pragma unroll
            for (int nt = 0; nt < 4; ++nt)
                #pragma unroll
                for (int j = 0; j < 4; ++j) vC[rb][nt][j] = acc[rb][nt][j];

        // Kerr: x in ntiles 0,1; p in ntiles 2,3 (same reg index)
        if (l < N_LAYERS - 1) {
            float4 kf = __ldg(&g_kf[l][lane]);
            #pragma unroll
            for (int rb = 0; rb < 2; ++rb)
                #pragma unroll
                for (int nt = 0; nt < 2; ++nt)
                    #pragma unroll
                    for (int j = 0; j < 4; ++j) {
                        float kp = nt ? ((j & 1) ? kf.w : kf.z)
                                      : ((j & 1) ? kf.y : kf.x);
                        float x = vC[rb][nt][j], p = vC[rb][nt + 2][j];
                        float ang = kp * (x * x + p * p);
                        float s, c;
                        __sincosf(ang, &s, &c);
                        vC[rb][nt][j]     = fmaf(c, x,  s * p);
                        vC[rb][nt + 2][j] = fmaf(c, p, -s * x);
                    }
        }
    }

    // ---- last activation + store ----
    float4 kf = __ldg(&g_kf[N_LAYERS - 1][lane]);
    #pragma unroll
    for (int rb = 0; rb < 2; ++rb) {
        float o0[4], o1[4];
        #pragma unroll
        for (int j = 0; j < 4; ++j) {
            float kp = (j & 1) ? kf.y : kf.x;
            float x = vC[rb][0][j], p = vC[rb][2][j];
            float ang = kp * (x * x + p * p);
            float s, c;
            __sincosf(ang, &s, &c);
            o0[j] = fmaf(c, x, s * p);
            kp = (j & 1) ? kf.w : kf.z;
            x = vC[rb][1][j]; p = vC[rb][3][j];
            ang = kp * (x * x + p * p);
            __sincosf(ang, &s, &c);
            o1[j] = fmaf(c, x, s * p);
        }
        #pragma unroll
        for (int h = 0; h < 2; ++h) {
            int row = r[rb][h];
            if (row < n_samples) {
                *reinterpret_cast<float2*>(out + (size_t)row * OUT_COLS + c0) =
                    make_float2(o0[2 * h], o0[2 * h + 1]);
                if (c0 == 0)
                    *reinterpret_cast<float2*>(out + (size_t)row * OUT_COLS + 8) =
                        make_float2(o1[2 * h], o1[2 * h + 1]);
            }
        }
    }
}

// ---------------------------------------------------------------------------
extern "C" void kernel_launch(void* const* d_in, const int* in_sizes, int n_in,
                              void* d_out, int out_size) {
    const float* batch    = (const float*)d_in[0];   // (B,16)
    const float* lin      = (const float*)d_in[1];   // (6,528)
    const float* act_p    = (const float*)d_in[2];   // (5,16)
    const float* last_act = (const float*)d_in[3];   // (16,)
    float* out = (float*)d_out;

    int n_samples = in_sizes[0] / N_MODES;
    int blocks = (n_samples + 127) / 128;

    setup_kernel<<<1, 1024>>>(lin, act_p, last_act);
    qnet_main<<<blocks, TPB>>>(batch, out, n_samples);
}

// round 16
// speedup vs baseline: 3.0686x; 1.2051x over previous
#include <cuda_runtime.h>
#include <cuda_bf16.h>

#define N_MODES   16
#define N_LAYERS  6
#define LIN_P     528
#define OUT_COLS  10
#define TPB       128            // 4 warps x 32 samples -> 128 samples/CTA

// ---------------------------------------------------------------------------
// Device-global parameter fragments (allocation-free per harness rules)
// ---------------------------------------------------------------------------
__device__ uint2  g_Bf[N_LAYERS][2][4][32];   // B frags [layer][ktile][ntile][lane]
__device__ float4 g_df[N_LAYERS][2][32];      // d frags [layer][half][lane]
__device__ float4 g_kf[N_LAYERS][32];         // kerr frags [layer][lane]

// ---------------------------------------------------------------------------
// helpers
// ---------------------------------------------------------------------------
__device__ __forceinline__ unsigned pack_bf16x2(float lo, float hi) {
    unsigned r;
    asm("cvt.rn.bf16x2.f32 %0, %1, %2;" : "=r"(r) : "f"(hi), "f"(lo));
    return r;
}
__device__ __forceinline__ void mma16816(float& c0, float& c1, float& c2, float& c3,
                                         unsigned a0, unsigned a1, unsigned a2, unsigned a3,
                                         unsigned b0, unsigned b1) {
    asm("mma.sync.aligned.m16n8k16.row.col.f32.bf16.bf16.f32 "
        "{%0,%1,%2,%3}, {%4,%5,%6,%7}, {%8,%9}, {%0,%1,%2,%3};"
        : "+f"(c0), "+f"(c1), "+f"(c2), "+f"(c3)
        : "r"(a0), "r"(a1), "r"(a2), "r"(a3), "r"(b0), "r"(b1));
}

// ---------------------------------------------------------------------------
// Setup kernel: ONE BLOCK PER LAYER (6 blocks, layers fully independent).
// Scans go straight to smem (no g_S round-trip); compose E = W - I; pack
// B/d/kerr fragments for this layer.
// ---------------------------------------------------------------------------
__global__ void setup_kernel(const float* __restrict__ lin,
                             const float* __restrict__ act_p,
                             const float* __restrict__ last_act) {
    int tid = threadIdx.x;
    int l   = blockIdx.x;                 // layer
    __shared__ float s_scale[32];
    __shared__ float sS1[32][33];         // S1[row][col] padded
    __shared__ float sS2[32][33];         // S2[row][col] padded
    __shared__ float sE[32][33];          // E[o][i] padded

    const float* lp = lin + l * LIN_P;

    if (tid < 32) {
        // ---- interferometer scan: w = which (0=S1, 1=S2), col = U column ----
        int w   = tid >> 4;
        int col = tid & 15;
        const float* th = lp + (w ? 256 : 0);
        const float* ph = lp + (w ? 376 : 120);

        float ur[16], ui[16];
        #pragma unroll
        for (int m = 0; m < 16; ++m) { ur[m] = (m == col) ? 1.f : 0.f; ui[m] = 0.f; }
        int k = 0;
        #pragma unroll
        for (int i = 0; i < 16; ++i) {
            #pragma unroll
            for (int j = i + 1; j < 16; ++j) {
                float t = th[k], p = ph[k];
                float s, c, sp, cp;
                __sincosf(t, &s, &c);
                __sincosf(p, &sp, &cp);
                float br = cp * s, bi = sp * s;
                float air = ur[i], aii = ui[i];
                float ajr = ur[j], aji = ui[j];
                ur[i] = c * air - (br * ajr + bi * aji);
                ui[i] = c * aii - (br * aji - bi * ajr);
                ur[j] = (br * air - bi * aii) + c * ajr;
                ui[j] = (br * aii + bi * air) + c * aji;
                ++k;
            }
        }
        float (*dst)[33] = w ? sS2 : sS1;
        #pragma unroll
        for (int m = 0; m < 16; ++m) {
            dst[m][col]           =  ur[m];
            dst[m][col + 16]      = -ui[m];
            dst[m + 16][col]      =  ui[m];
            dst[m + 16][col + 16] =  ur[m];
        }
    } else if (tid < 64) {
        int kk = tid - 32;
        float r = lp[240 + (kk & 15)];
        s_scale[kk] = __expf(kk < 16 ? -r : r);
    }
    __syncthreads();

    // ---- compose E = S2*diag(scale)*S1 - I  (1024 threads: o=warp, i=lane) ----
    {
        int o = tid >> 5, i = tid & 31;
        float acc = 0.f;
        #pragma unroll
        for (int k = 0; k < 32; ++k)
            acc += sS2[o][k] * (s_scale[k] * sS1[k][i]);
        sE[o][i] = acc - ((i == o) ? 1.f : 0.f);
    }
    __syncthreads();

    // ---- pack B fragments: 2 kt x 4 nt x 32 lanes = 256 threads ----
    if (tid < 256) {
        int lane = tid & 31;
        int nt   = (tid >> 5) & 3;
        int kt   = tid >> 7;
        int n    = nt * 8 + (lane >> 2);
        int k0   = kt * 16 + 2 * (lane & 3);
        uint2 b;
        b.x = pack_bf16x2(sE[n][k0],     sE[n][k0 + 1]);
        b.y = pack_bf16x2(sE[n][k0 + 8], sE[n][k0 + 9]);
        g_Bf[l][kt][nt][lane] = b;
    } else if (tid < 320) {
        // ---- d fragments: 2 halves x 32 lanes ----
        int lane = tid & 31, half = (tid >> 5) & 1;
        int c0 = 2 * (lane & 3) + half * 16;
        g_df[l][half][lane] = make_float4(lp[496 + c0],     lp[496 + c0 + 1],
                                          lp[496 + c0 + 8], lp[496 + c0 + 9]);
    } else if (tid < 352) {
        // ---- kerr fragments ----
        int lane = tid & 31;
        const float* kp = (l < N_LAYERS - 1) ? (act_p + l * 16) : last_act;
        int c0 = 2 * (lane & 3);
        g_kf[l][lane] = make_float4(kp[c0], kp[c0 + 1], kp[c0 + 8], kp[c0 + 9]);
    }
}

// ---------------------------------------------------------------------------
// Main kernel: warp = 32 samples (2 row-blocks); in-place MMA accumulation
// (pack A from old v, v += d, MMA accumulates into v -- no acc copy).
// ---------------------------------------------------------------------------
__global__ void __launch_bounds__(TPB) qnet_main(
    const float* __restrict__ batch,
    float* __restrict__ out,
    int n_samples)
{
    int tid  = threadIdx.x;
    int warp = tid >> 5;
    int lane = tid & 31;
    int qr   = lane >> 2;                 // row-in-tile 0..7
    int c0   = 2 * (lane & 3);            // col base within n-tile

    int base = blockIdx.x * 128 + warp * 32;
    int r[2][2];
    r[0][0] = base + qr;       r[0][1] = base + qr + 8;
    r[1][0] = base + 16 + qr;  r[1][1] = base + 16 + qr + 8;

    // ---- load input into C-fragment layout: vC[rb][nt][j] ----
    float vC[2][4][4];
    #pragma unroll
    for (int rb = 0; rb < 2; ++rb) {
        #pragma unroll
        for (int nt = 0; nt < 2; ++nt) {
            float2 t0 = (r[rb][0] < n_samples)
                ? *reinterpret_cast<const float2*>(batch + (size_t)r[rb][0] * 16 + nt * 8 + c0)
                : make_float2(0.f, 0.f);
            float2 t1 = (r[rb][1] < n_samples)
                ? *reinterpret_cast<const float2*>(batch + (size_t)r[rb][1] * 16 + nt * 8 + c0)
                : make_float2(0.f, 0.f);
            vC[rb][nt][0] = t0.x; vC[rb][nt][1] = t0.y;
            vC[rb][nt][2] = t1.x; vC[rb][nt][3] = t1.y;
        }
        #pragma unroll
        for (int nt = 2; nt < 4; ++nt)
            #pragma unroll
            for (int j = 0; j < 4; ++j) vC[rb][nt][j] = 0.f;
    }

    #pragma unroll
    for (int l = 0; l < N_LAYERS; ++l) {
        const int klim = (l == 0) ? 1 : 2;

        // 1) pack A fragments from the CURRENT state (before adding d)
        unsigned a[2][2][4];                      // [kt][rb][reg]
        #pragma unroll
        for (int kt = 0; kt < 2; ++kt) {
            if (kt >= klim) break;
            #pragma unroll
            for (int rb = 0; rb < 2; ++rb) {
                a[kt][rb][0] = pack_bf16x2(vC[rb][2 * kt][0],     vC[rb][2 * kt][1]);
                a[kt][rb][1] = pack_bf16x2(vC[rb][2 * kt][2],     vC[rb][2 * kt][3]);
                a[kt][rb][2] = pack_bf16x2(vC[rb][2 * kt + 1][0], vC[rb][2 * kt + 1][1]);
                a[kt][rb][3] = pack_bf16x2(vC[rb][2 * kt + 1][2], vC[rb][2 * kt + 1][3]);
            }
        }

        // 2) v += d (in place)
        {
            float4 d0 = __ldg(&g_df[l][0][lane]);
            float4 d1 = __ldg(&g_df[l][1][lane]);
            #pragma unroll
            for (int rb = 0; rb < 2; ++rb) {
                vC[rb][0][0] += d0.x; vC[rb][0][1] += d0.y;
                vC[rb][0][2] += d0.x; vC[rb][0][3] += d0.y;
                vC[rb][1][0] += d0.z; vC[rb][1][1] += d0.w;
                vC[rb][1][2] += d0.z; vC[rb][1][3] += d0.w;
                vC[rb][2][0] += d1.x; vC[rb][2][1] += d1.y;
                vC[rb][2][2] += d1.x; vC[rb][2][3] += d1.y;
                vC[rb][3][0] += d1.z; vC[rb][3][1] += d1.w;
                vC[rb][3][2] += d1.z; vC[rb][3][3] += d1.w;
            }
        }

        // 3) v += E @ v_old  (MMA accumulates directly into vC)
        #pragma unroll
        for (int kt = 0; kt < 2; ++kt) {
            if (kt >= klim) break;
            #pragma unroll
            for (int nt = 0; nt < 4; ++nt) {
                uint2 b = __ldg(&g_Bf[l][kt][nt][lane]);
                #pragma unroll
                for (int rb = 0; rb < 2; ++rb)
                    mma16816(vC[rb][nt][0], vC[rb][nt][1], vC[rb][nt][2], vC[rb][nt][3],
                             a[kt][rb][0], a[kt][rb][1], a[kt][rb][2], a[kt][rb][3],
                             b.x, b.y);
            }
        }

        // 4) Kerr: x in ntiles 0,1; p in ntiles 2,3 (same reg index)
        if (l < N_LAYERS - 1) {
            float4 kf = __ldg(&g_kf[l][lane]);
            #pragma unroll
            for (int rb = 0; rb < 2; ++rb)
                #pragma unroll
                for (int nt = 0; nt < 2; ++nt)
                    #pragma unroll
                    for (int j = 0; j < 4; ++j) {
                        float kp = nt ? ((j & 1) ? kf.w : kf.z)
                                      : ((j & 1) ? kf.y : kf.x);
                        float x = vC[rb][nt][j], p = vC[rb][nt + 2][j];
                        float ang = kp * (x * x + p * p);
                        float s, c;
                        __sincosf(ang, &s, &c);
                        vC[rb][nt][j]     = fmaf(c, x,  s * p);
                        vC[rb][nt + 2][j] = fmaf(c, p, -s * x);
                    }
        }
    }

    // ---- last activation + store ----
    float4 kf = __ldg(&g_kf[N_LAYERS - 1][lane]);
    #pragma unroll
    for (int rb = 0; rb < 2; ++rb) {
        float o0[4], o1[4];
        #pragma unroll
        for (int j = 0; j < 4; ++j) {
            float kp = (j & 1) ? kf.y : kf.x;
            float x = vC[rb][0][j], p = vC[rb][2][j];
            float ang = kp * (x * x + p * p);
            float s, c;
            __sincosf(ang, &s, &c);
            o0[j] = fmaf(c, x, s * p);
            kp = (j & 1) ? kf.w : kf.z;
            x = vC[rb][1][j]; p = vC[rb][3][j];
            ang = kp * (x * x + p * p);
            __sincosf(ang, &s, &c);
            o1[j] = fmaf(c, x, s * p);
        }
        #pragma unroll
        for (int h = 0; h < 2; ++h) {
            int row = r[rb][h];
            if (row < n_samples) {
                *reinterpret_cast<float2*>(out + (size_t)row * OUT_COLS + c0) =
                    make_float2(o0[2 * h], o0[2 * h + 1]);
                if (c0 == 0)
                    *reinterpret_cast<float2*>(out + (size_t)row * OUT_COLS + 8) =
                        make_float2(o1[2 * h], o1[2 * h + 1]);
            }
        }
    }
}

// ---------------------------------------------------------------------------
extern "C" void kernel_launch(void* const* d_in, const int* in_sizes, int n_in,
                              void* d_out, int out_size) {
    const float* batch    = (const float*)d_in[0];   // (B,16)
    const float* lin      = (const float*)d_in[1];   // (6,528)
    const float* act_p    = (const float*)d_in[2];   // (5,16)
    const float* last_act = (const float*)d_in[3];   // (16,)
    float* out = (float*)d_out;

    int n_samples = in_sizes[0] / N_MODES;
    int blocks = (n_samples + 127) / 128;

    setup_kernel<<<N_LAYERS, 1024>>>(lin, act_p, last_act);
    qnet_main<<<blocks, TPB>>>(batch, out, n_samples);
}